// round 11
// baseline (speedup 1.0000x reference)
#include <cuda_runtime.h>
#include <math.h>
#include <stdint.h>

// Problem constants
#define TLEN 4096
#define BSZ 8

typedef unsigned long long ull;

// Packed fp32x2 helpers
#define FMA2(acc, a, b) \
    asm("fma.rn.f32x2 %0, %1, %2, %3;" : "=l"(acc) : "l"(a), "l"(b), "l"(acc))
#define PACKB(d, s) \
    asm("mov.b64 %0, {%1, %1};" : "=l"(d) : "f"(s))
#define PACK2(d, lo, hi) \
    asm("mov.b64 %0, {%1, %2};" : "=l"(d) : "f"(lo), "f"(hi))
#define UNPACK2(lo, hi, s) \
    asm("mov.b64 {%0, %1}, %2;" : "=f"(lo), "=f"(hi) : "l"(s))

// cp.async primitives
__device__ __forceinline__ void cp4(uint32_t dst, const float* src, bool ok) {
    int sz = ok ? 4 : 0;
    asm volatile("cp.async.ca.shared.global [%0], [%1], 4, %2;"
                 :: "r"(dst), "l"(src), "r"(sz));
}
__device__ __forceinline__ void cp16(uint32_t dst, const void* src) {
    asm volatile("cp.async.cg.shared.global [%0], [%1], 16;"
                 :: "r"(dst), "l"(src));
}
#define CP_COMMIT() asm volatile("cp.async.commit_group;")
#define CP_WAIT(N) asm volatile("cp.async.wait_group %0;" :: "n"(N))

__device__ __forceinline__ int swz(int c) { return c ^ ((c >> 3) & 3); }
__device__ __forceinline__ int swzf(int p) { return (swz(p >> 2) << 2) | (p & 3); }

__device__ __forceinline__ uint32_t smem_u32(const void* p) {
    return (uint32_t)__cvta_generic_to_shared(p);
}

// tf32 mma (sm_80+ PTX; compiles on base sm_100 target — verified round 9)
__device__ __forceinline__ void mma_tf32(float c[4], const uint32_t a[4],
                                         uint32_t b0, uint32_t b1) {
    asm volatile(
        "mma.sync.aligned.m16n8k8.row.col.f32.tf32.tf32.f32 "
        "{%0,%1,%2,%3}, {%4,%5,%6,%7}, {%8,%9}, {%0,%1,%2,%3};"
        : "+f"(c[0]), "+f"(c[1]), "+f"(c[2]), "+f"(c[3])
        : "r"(a[0]), "r"(a[1]), "r"(a[2]), "r"(a[3]), "r"(b0), "r"(b1));
}

// order-preserving float<->uint encoding (for smem atomicMin on dists)
__device__ __forceinline__ unsigned encf(float f) {
    unsigned b = __float_as_uint(f);
    return (b & 0x80000000u) ? ~b : (b | 0x80000000u);
}
__device__ __forceinline__ float decf(unsigned u) {
    return __uint_as_float((u & 0x80000000u) ? (u & 0x7FFFFFFFu) : ~u);
}

// ---------------- device scratch ----------------
__device__ float g_x1[BSZ * 64 * TLEN];
__device__ float g_x2[BSZ * 128 * TLEN];
__device__ float g_x3[BSZ * 256 * TLEN];
__device__ float g_x4[BSZ * 512 * TLEN];
__device__ float g_x5[BSZ * 512 * TLEN];
__device__ float g_zqT[BSZ * 512 * TLEN];
__device__ float g_w2T[64 * 5 * 128];
__device__ float g_w3T[128 * 5 * 256];
__device__ float g_w4T[256 * 3 * 512];
__device__ float g_w5T[512 * 3 * 512];
__device__ float g_hwT[512 * 256];
__device__ float g_cnorm[8 * 1024];
__device__ float g_cnmax[8];
__device__ float g_part[2048];

#define OFF_A 0
#define OFF_B (BSZ * 8 * TLEN)
#define OFF_L (OFF_B + BSZ * 4 * TLEN * 64)

// ---------------- prep (round-5 proven) ----------------
__device__ __forceinline__ void tr_seg(int local, const float* __restrict__ w,
                                       float* __restrict__ wT, int CIN, int COUT, int K) {
    int co = local % COUT;
    int j = (local / COUT) % K;
    int ci = local / (COUT * K);
    wT[local] = w[((size_t)co * CIN + ci) * K + j];
}
#define N_W2 (64 * 5 * 128)
#define N_W3 (128 * 5 * 256)
#define N_W4 (256 * 3 * 512)
#define N_W5 (512 * 3 * 512)
#define N_HW (512 * 256)
#define N_CN (8 * 1024)
#define N_PREP (N_W2 + N_W3 + N_W4 + N_W5 + N_HW + N_CN)

__global__ void prep_kernel(const float* __restrict__ w2, const float* __restrict__ w3,
                            const float* __restrict__ w4, const float* __restrict__ w5,
                            const float* __restrict__ hw, const float* __restrict__ cbk,
                            float* __restrict__ w2T, float* __restrict__ w3T,
                            float* __restrict__ w4T, float* __restrict__ w5T,
                            float* __restrict__ hwT, float* __restrict__ cnorm) {
    int i = blockIdx.x * 256 + threadIdx.x;
    if (i < N_W2) { tr_seg(i, w2, w2T, 64, 128, 5); return; }
    i -= N_W2;
    if (i < N_W3) { tr_seg(i, w3, w3T, 128, 256, 5); return; }
    i -= N_W3;
    if (i < N_W4) { tr_seg(i, w4, w4T, 256, 512, 3); return; }
    i -= N_W4;
    if (i < N_W5) { tr_seg(i, w5, w5T, 512, 512, 3); return; }
    i -= N_W5;
    if (i < N_HW) {
        int co = i % 256, d = i / 256;
        int h = co >> 6, v = co & 63;
        hwT[i] = hw[((size_t)h * 512 + d) * 64 + v];
        return;
    }
    i -= N_HW;
    if (i < N_CN) {
        const float* row = cbk + (size_t)i * 64;
        float s = 0.f;
#pragma unroll 8
        for (int d = 0; d < 64; d++) { float v = row[d]; s += v * v; }
        cnorm[i] = s;
    }
}

__global__ void gmax_kernel(const float* __restrict__ cnorm, float* __restrict__ cnmax) {
    __shared__ float s[256];
    int g = blockIdx.x, tid = threadIdx.x;
    float m = 0.f;
    for (int i = tid; i < 1024; i += 256) m = fmaxf(m, cnorm[g * 1024 + i]);
    s[tid] = m;
    __syncthreads();
    for (int k = 128; k > 0; k >>= 1) {
        if (tid < k) s[tid] = fmaxf(s[tid], s[tid + k]);
        __syncthreads();
    }
    if (tid == 0) cnmax[g] = s[0];
}

// ---------------- conv1 (round-5 proven) ----------------
__global__ void conv1_kernel(const float* __restrict__ audio, const float* __restrict__ w1,
                             const float* __restrict__ b1, float* __restrict__ y) {
    __shared__ float sx[134], sw[448], sbv[64];
    const int b = blockIdx.y, t0 = blockIdx.x * 128, tid = threadIdx.x;
    for (int i = tid; i < 134; i += 128) {
        int t = t0 - 6 + i;
        sx[i] = (t >= 0) ? audio[(size_t)b * TLEN + t] : 0.f;
    }
    for (int i = tid; i < 448; i += 128) sw[i] = w1[i];
    if (tid < 64) sbv[tid] = b1[tid];
    __syncthreads();
    float xv[7];
#pragma unroll
    for (int j = 0; j < 7; j++) xv[j] = sx[tid + j];
    for (int c = 0; c < 64; c++) {
        float acc = sbv[c];
#pragma unroll
        for (int j = 0; j < 7; j++) acc += sw[c * 7 + j] * xv[j];
        acc = acc > 0.f ? acc : expm1f(acc);
        y[((size_t)b * 64 + c) * TLEN + t0 + tid] = acc;
    }
}

// ---- conv-as-GEMM, round-5 proven (f32x2, 3-stage cp.async) ----
template <int CIN, int COUT, int K, int CI_CHUNK, int ELU, int HEAD>
__global__ __launch_bounds__(256, 2)
void conv_gemm(const float* __restrict__ x, const float* __restrict__ wT,
               const float* __restrict__ bias, float* __restrict__ y) {
    constexpr int XROW = 136;
    constexpr int NX = 8 + K - 1;
    constexpr int NXF4 = (NX + 3) / 4;
    constexpr int XS_FL = CI_CHUNK * XROW;
    constexpr int WS_FL = CI_CHUNK * K * 128;
    constexpr int STG_FL = XS_FL + WS_FL;
    constexpr int NCHUNK = CIN / CI_CHUNK;

    extern __shared__ float smem[];
    const uint32_t sb = smem_u32(smem);
    const int b = blockIdx.z, t0 = blockIdx.x * 128, co0 = blockIdx.y * 128;
    const int tid = threadIdx.x;
    const int tx = tid & 15, ty = tid >> 4;
    const int tb = tx * 8, cb = ty * 8;

    auto load_chunk = [&](int c, int st) {
        const int ci0 = c * CI_CHUNK;
        uint32_t xbB = sb + (uint32_t)(st * STG_FL) * 4u;
        for (int i = tid; i < XS_FL; i += 256) {
            int cc = i / XROW, p = i % XROW;
            int t = t0 - (K - 1) + p;
            bool ok = (t >= 0) && (t < TLEN);
            const float* src = x + ((size_t)b * CIN + ci0 + cc) * TLEN + (ok ? t : 0);
            cp4(xbB + (uint32_t)(cc * XROW + swzf(p)) * 4u, src, ok);
        }
        uint32_t wbB = xbB + (uint32_t)XS_FL * 4u;
        for (int i4 = tid * 4; i4 < WS_FL; i4 += 1024) {
            int cc = i4 / (K * 128);
            int rem = i4 % (K * 128);
            int j = rem / 128, co = rem % 128;
            cp16(wbB + (uint32_t)i4 * 4u,
                 wT + ((size_t)(ci0 + cc) * K + j) * COUT + co0 + co);
        }
        CP_COMMIT();
    };

    load_chunk(0, 0);
    if (NCHUNK > 1) load_chunk(1, 1);

    ull acc2[4][8];
#pragma unroll
    for (int rp = 0; rp < 4; rp++) {
        ull bb2;
        PACK2(bb2, bias[co0 + cb + 2 * rp], bias[co0 + cb + 2 * rp + 1]);
#pragma unroll
        for (int lt = 0; lt < 8; lt++) acc2[rp][lt] = bb2;
    }

    int st = 0;
#pragma unroll 1
    for (int c = 0; c < NCHUNK; c++) {
        if (c + 1 < NCHUNK) { CP_WAIT(1); } else { CP_WAIT(0); }
        __syncthreads();
        if (c + 2 < NCHUNK) {
            int st2 = st + 2; if (st2 >= 3) st2 -= 3;
            load_chunk(c + 2, st2);
        }
        const float* xsb = smem + st * STG_FL;
        const float* wsb = xsb + XS_FL;
#pragma unroll 1
        for (int cc = 0; cc < CI_CHUNK; cc++) {
            const float* xrow = xsb + cc * XROW;
            float xv[NXF4 * 4];
#pragma unroll
            for (int q = 0; q < NXF4; q++)
                *(float4*)&xv[q * 4] = *(const float4*)&xrow[swz(tx * 2 + q) << 2];
            ull xb[NX];
#pragma unroll
            for (int p = 0; p < NX; p++) PACKB(xb[p], xv[p]);
#pragma unroll
            for (int j = 0; j < K; j++) {
                const float* wrow = wsb + (cc * K + j) * 128 + cb;
                ulonglong2 w01 = *(const ulonglong2*)&wrow[0];
                ulonglong2 w23 = *(const ulonglong2*)&wrow[4];
                ull wp[4] = {w01.x, w01.y, w23.x, w23.y};
#pragma unroll
                for (int rp = 0; rp < 4; rp++)
#pragma unroll
                    for (int lt = 0; lt < 8; lt++)
                        FMA2(acc2[rp][lt], wp[rp], xb[lt + j]);
            }
        }
        if (++st == 3) st = 0;
    }

    float accs[8][8];
#pragma unroll
    for (int rp = 0; rp < 4; rp++)
#pragma unroll
        for (int lt = 0; lt < 8; lt++)
            UNPACK2(accs[2 * rp][lt], accs[2 * rp + 1][lt], acc2[rp][lt]);

    if (HEAD) {
        const int h = (co0 + cb) >> 6;
        const int v0 = (co0 + cb) & 63;
#pragma unroll
        for (int lt = 0; lt < 8; lt++) {
            int t = t0 + tb + lt;
            float4 o0 = make_float4(accs[0][lt], accs[1][lt], accs[2][lt], accs[3][lt]);
            float4 o1 = make_float4(accs[4][lt], accs[5][lt], accs[6][lt], accs[7][lt]);
            float* base = &y[(((size_t)b * 4 + h) * TLEN + t) * 64 + v0];
            *(float4*)base = o0;
            *(float4*)(base + 4) = o1;
        }
    } else {
#pragma unroll
        for (int r = 0; r < 8; r++) {
            float o[8];
#pragma unroll
            for (int lt = 0; lt < 8; lt++) {
                float a = accs[r][lt];
                if (ELU) a = a > 0.f ? a : expm1f(a);
                o[lt] = a;
            }
            float* base = &y[((size_t)b * COUT + co0 + cb + r) * TLEN + t0 + tb];
            *(float4*)base = *(float4*)&o[0];
            *(float4*)(base + 4) = *(float4*)&o[4];
        }
    }
}

// ------------- VQ v2: tf32-mma coarse + exact fp32 refine -------------
// Block: (t-chunk 128 tokens, g, b), 256 threads.
// All tile rows stride 68 floats (272B: 16B-aligned for cp16, conflict-free
// for fragment loads: bank = (4*row + lc) % 32 covers all 32 banks).
#define CAP 8
#define AST 68
#define V2_AS 0                               // 128*68 = 8704
#define V2_BS 8704                            // 2 x 8704
#define V2_CNS 26112                          // 2 x 128
#define V2_ZN 26368
#define V2_BAND 26496
#define V2_RMIN 26624
#define V2_CNT 26752
#define V2_CAND 26880                         // 128*8 = 1024
#define V2_OVFN 27904
#define V2_OVFL 27908                         // 128
#define V2_FLOATS 28036
#define V2_BYTES (V2_FLOATS * 4)              // 112144
// aliases (dead regions after their phases):
#define V2_REDV V2_CAND
#define V2_REDI (V2_CAND + 256)
#define V2_QS V2_BS

__global__ __launch_bounds__(256)
void vq2_kernel(const float* __restrict__ x5, const float* __restrict__ cbk,
                const float* __restrict__ cnormG, const float* __restrict__ cnmaxG,
                float* __restrict__ zqT, float* __restrict__ out_a,
                float* __restrict__ partial) {
    extern __shared__ float sm[];
    const uint32_t sb = smem_u32(sm);
    float* As = sm + V2_AS;                 // [128][68] z t-major
    float* Bs = sm + V2_BS;                 // [2][128][68] code chunks
    float* cnS = sm + V2_CNS;               // [2][128]
    float* zn = sm + V2_ZN;
    float* band = sm + V2_BAND;
    unsigned* runmin = (unsigned*)(sm + V2_RMIN);
    int* cnt = (int*)(sm + V2_CNT);
    int* cand = (int*)(sm + V2_CAND);
    int* ovfn = (int*)(sm + V2_OVFN);
    int* ovfl = (int*)(sm + V2_OVFL);
    float* redv = sm + V2_REDV;             // aliases cand (dead by then)
    int* redi = (int*)(sm + V2_REDI);
    int* besti = (int*)runmin;              // alias after coarse
    float* qs = sm + V2_QS;                 // alias after refine

    const int b = blockIdx.z, g = blockIdx.y;
    const int t0 = blockIdx.x * 128;
    const int tid = threadIdx.x, lane = tid & 31, wid = tid >> 5;
    const int wm = wid & 1, wn = wid >> 1;  // 2m x 4n warps; warp tile m64 x n32
    const int lr = lane >> 2, lc = lane & 3;

    auto loadB = [&](int c, int bf) {
        const int k0 = c << 7;
        uint32_t bB = sb + (uint32_t)(V2_BS + bf * 8704) * 4u;
        for (int i = tid; i < 2048; i += 256) {
            int r = i >> 4, u = i & 15;
            cp16(bB + (uint32_t)(r * AST + u * 4) * 4u,
                 cbk + ((size_t)g * 1024 + k0 + r) * 64 + u * 4);
        }
        if (tid < 32)
            cp16(sb + (uint32_t)(V2_CNS + bf * 128 + tid * 4) * 4u,
                 cnormG + g * 1024 + k0 + tid * 4);
        CP_COMMIT();
    };

    // group0: As (z transpose, cp4 — 4B aligned by construction) + B chunk 0
    for (int i = tid; i < 8192; i += 256) {
        int d = i >> 7, lt = i & 127;
        cp4(sb + (uint32_t)(V2_AS + lt * AST + d) * 4u,
            x5 + (((size_t)b * 512) + (g << 6) + d) * TLEN + t0 + lt, true);
    }
    loadB(0, 0);

    const float cnmax = cnmaxG[g];

#pragma unroll 1
    for (int c = 0; c < 8; c++) {
        if (c + 1 < 8) { loadB(c + 1, (c + 1) & 1); CP_WAIT(1); } else { CP_WAIT(0); }
        __syncthreads();

        if (c == 0) {
            if (tid < 128) {
                float s = 0.f;
#pragma unroll 8
                for (int d = 0; d < 64; d++) {
                    float v = As[tid * AST + d];
                    s += v * v;                       // ascending-d, matches proven order
                }
                zn[tid] = s;
                band[tid] = 0.03125f * sqrtf(s * cnmax);
                runmin[tid] = 0xFF800000u;            // enc(+inf)
                cnt[tid] = 0;
            }
            if (tid == 0) *ovfn = 0;
            __syncthreads();
        }

        const float* B = Bs + (c & 1) * 8704;
        const float* cn_ = cnS + (c & 1) * 128;

        float acc[4][4][4];
#pragma unroll
        for (int mt = 0; mt < 4; mt++)
#pragma unroll
            for (int nt = 0; nt < 4; nt++)
#pragma unroll
                for (int v = 0; v < 4; v++) acc[mt][nt][v] = 0.f;

#pragma unroll
        for (int ks = 0; ks < 8; ks++) {
            const int k0 = ks * 8;
            uint32_t af[4][4], bf[4][2];
#pragma unroll
            for (int mt = 0; mt < 4; mt++) {
                const float* p = As + (wm * 64 + mt * 16 + lr) * AST + k0 + lc;
                af[mt][0] = __float_as_uint(p[0]);
                af[mt][1] = __float_as_uint(p[8 * AST]);
                af[mt][2] = __float_as_uint(p[4]);
                af[mt][3] = __float_as_uint(p[8 * AST + 4]);
            }
#pragma unroll
            for (int nt = 0; nt < 4; nt++) {
                const float* p = B + (wn * 32 + nt * 8 + lr) * AST + k0 + lc;
                bf[nt][0] = __float_as_uint(p[0]);
                bf[nt][1] = __float_as_uint(p[4]);
            }
#pragma unroll
            for (int mt = 0; mt < 4; mt++)
#pragma unroll
                for (int nt = 0; nt < 4; nt++)
                    mma_tf32(acc[mt][nt], af[mt], bf[nt][0], bf[nt][1]);
        }

        // phase 1: per-thread token minima -> atomicMin
#pragma unroll
        for (int mt = 0; mt < 4; mt++) {
            int r0 = wm * 64 + mt * 16 + lr;
            float m0 = 3.4e38f, m1 = 3.4e38f;
#pragma unroll
            for (int nt = 0; nt < 4; nt++) {
                int kk = wn * 32 + nt * 8 + 2 * lc;
                float c0 = cn_[kk], c1 = cn_[kk + 1];
                m0 = fminf(m0, fminf(zn[r0] + c0 - 2.f * acc[mt][nt][0],
                                     zn[r0] + c1 - 2.f * acc[mt][nt][1]));
                m1 = fminf(m1, fminf(zn[r0 + 8] + c0 - 2.f * acc[mt][nt][2],
                                     zn[r0 + 8] + c1 - 2.f * acc[mt][nt][3]));
            }
            atomicMin(&runmin[r0], encf(m0));
            atomicMin(&runmin[r0 + 8], encf(m1));
        }
        __syncthreads();

        // phase 2: candidate collection (superset: runmin only decreases later,
        // band >= 2*eps_tf32 rigorously)
#pragma unroll
        for (int mt = 0; mt < 4; mt++) {
            int r0 = wm * 64 + mt * 16 + lr;
            float th0 = decf(runmin[r0]) + band[r0];
            float th1 = decf(runmin[r0 + 8]) + band[r0 + 8];
#pragma unroll
            for (int nt = 0; nt < 4; nt++) {
                int kk = wn * 32 + nt * 8 + 2 * lc;
                int kg = (c << 7) + kk;
                float c0 = cn_[kk], c1 = cn_[kk + 1];
                float d00 = zn[r0] + c0 - 2.f * acc[mt][nt][0];
                float d01 = zn[r0] + c1 - 2.f * acc[mt][nt][1];
                float d10 = zn[r0 + 8] + c0 - 2.f * acc[mt][nt][2];
                float d11 = zn[r0 + 8] + c1 - 2.f * acc[mt][nt][3];
                if (d00 <= th0) { int s = atomicAdd(&cnt[r0], 1); if (s < CAP) cand[r0 * CAP + s] = kg; }
                if (d01 <= th0) { int s = atomicAdd(&cnt[r0], 1); if (s < CAP) cand[r0 * CAP + s] = kg + 1; }
                if (d10 <= th1) { int s = atomicAdd(&cnt[r0 + 8], 1); if (s < CAP) cand[(r0 + 8) * CAP + s] = kg; }
                if (d11 <= th1) { int s = atomicAdd(&cnt[r0 + 8], 1); if (s < CAP) cand[(r0 + 8) * CAP + s] = kg + 1; }
            }
        }
        __syncthreads();
    }

    // exact refine: fp32 fmaf chain, d ascending == proven FMA2 per-lane order
    if (tid < 128) {
        int n = cnt[tid];
        if (n <= CAP) {
            float best = 3.4e38f;
            int bidx = 1 << 30;
            for (int s = 0; s < n; s++) {
                int k = cand[tid * CAP + s];
                const float* cr = cbk + ((size_t)g * 1024 + k) * 64;
                float acc = 0.f;
#pragma unroll 8
                for (int d = 0; d < 64; d++) acc = fmaf(As[tid * AST + d], cr[d], acc);
                float dist = zn[tid] + cnormG[g * 1024 + k] - 2.f * acc;
                if (dist < best || (dist == best && k < bidx)) { best = dist; bidx = k; }
            }
            besti[tid] = bidx;
        } else {
            int o = atomicAdd(ovfn, 1);
            ovfl[o] = tid;
        }
    }
    __syncthreads();

    // rare fallback: block-cooperative exact full scan (cand dead -> redv/redi ok)
    int novf = *ovfn;
    for (int o = 0; o < novf; o++) {
        int t = ovfl[o];
        float best = 3.4e38f;
        int bidx = 1 << 30;
        for (int k = tid; k < 1024; k += 256) {
            const float* cr = cbk + ((size_t)g * 1024 + k) * 64;
            float acc = 0.f;
#pragma unroll 8
            for (int d = 0; d < 64; d++) acc = fmaf(As[t * AST + d], cr[d], acc);
            float dist = zn[t] + cnormG[g * 1024 + k] - 2.f * acc;
            if (dist < best || (dist == best && k < bidx)) { best = dist; bidx = k; }
        }
        redv[tid] = best; redi[tid] = bidx;
        __syncthreads();
        for (int s = 128; s > 0; s >>= 1) {
            if (tid < s) {
                float v = redv[tid + s]; int ii = redi[tid + s];
                if (v < redv[tid] || (v == redv[tid] && ii < redi[tid])) {
                    redv[tid] = v; redi[tid] = ii;
                }
            }
            __syncthreads();
        }
        if (tid == 0) besti[t] = redi[0];
        __syncthreads();
    }

    if (tid < 128)
        out_a[((size_t)b * 8 + g) * TLEN + t0 + tid] = (float)besti[tid];
    __syncthreads();

    // gather q + exact loss + coalesced d-major z_q store (qs aliases Bs)
    float ls = 0.f;
    for (int i = tid; i < 64 * 128; i += 256) {
        int d = i & 63, lt = i >> 6;
        float qv = cbk[((size_t)g * 1024 + besti[lt]) * 64 + d];
        float df = qv - As[lt * AST + d];
        ls += df * df;
        qs[d * 132 + lt] = qv;
    }
    __syncthreads();
    for (int i = tid; i < 64 * 128; i += 256) {
        int lt = i & 127, d = i >> 7;
        zqT[(((size_t)b * 512) + (g << 6) + d) * TLEN + t0 + lt] = qs[d * 132 + lt];
    }
    redv[tid] = ls;
    __syncthreads();
    for (int s = 128; s > 0; s >>= 1) {
        if (tid < s) redv[tid] += redv[tid + s];
        __syncthreads();
    }
    if (tid == 0)
        partial[((size_t)b * 8 + g) * 32 + blockIdx.x] = redv[0];
}

__global__ void loss_kernel(const float* __restrict__ partial, float* __restrict__ out) {
    __shared__ float s[256];
    int tid = threadIdx.x;
    float v = 0.f;
    for (int i = tid; i < 2048; i += 256) v += partial[i];
    s[tid] = v;
    __syncthreads();
    for (int k = 128; k > 0; k >>= 1) {
        if (tid < k) s[tid] += s[tid + k];
        __syncthreads();
    }
    if (tid == 0) out[OFF_L] = s[0] * (1.f / (8.f * 4096.f * 64.f));
}

// ---------------- launch ----------------
extern "C" void kernel_launch(void* const* d_in, const int* in_sizes, int n_in,
                              void* d_out, int out_size) {
    const float* audio = (const float*)d_in[0];
    const float* w1 = (const float*)d_in[1];
    const float* b1 = (const float*)d_in[2];
    const float* w2 = (const float*)d_in[3];
    const float* b2 = (const float*)d_in[4];
    const float* w3 = (const float*)d_in[5];
    const float* b3 = (const float*)d_in[6];
    const float* w4 = (const float*)d_in[7];
    const float* b4 = (const float*)d_in[8];
    const float* w5 = (const float*)d_in[9];
    const float* b5 = (const float*)d_in[10];
    const float* codebooks = (const float*)d_in[11];
    const float* head_w = (const float*)d_in[12];
    const float* head_b = (const float*)d_in[13];
    float* out = (float*)d_out;

    float *x1, *x2, *x3, *x4, *x5, *zqT, *w2T, *w3T, *w4T, *w5T, *hwT, *cnm, *cmx, *part;
    cudaGetSymbolAddress((void**)&x1, g_x1);
    cudaGetSymbolAddress((void**)&x2, g_x2);
    cudaGetSymbolAddress((void**)&x3, g_x3);
    cudaGetSymbolAddress((void**)&x4, g_x4);
    cudaGetSymbolAddress((void**)&x5, g_x5);
    cudaGetSymbolAddress((void**)&zqT, g_zqT);
    cudaGetSymbolAddress((void**)&w2T, g_w2T);
    cudaGetSymbolAddress((void**)&w3T, g_w3T);
    cudaGetSymbolAddress((void**)&w4T, g_w4T);
    cudaGetSymbolAddress((void**)&w5T, g_w5T);
    cudaGetSymbolAddress((void**)&hwT, g_hwT);
    cudaGetSymbolAddress((void**)&cnm, g_cnorm);
    cudaGetSymbolAddress((void**)&cmx, g_cnmax);
    cudaGetSymbolAddress((void**)&part, g_part);

    const int SM_C2 = (3 * (8 * 136 + 8 * 5 * 128)) * 4;
    const int SM_C3 = SM_C2;
    const int SM_C4 = (3 * (16 * 136 + 16 * 3 * 128)) * 4;
    const int SM_C5 = SM_C4;
    const int SM_HD = (3 * (16 * 136 + 16 * 1 * 128)) * 4;

    cudaFuncSetAttribute((const void*)conv_gemm<64, 128, 5, 8, 1, 0>,
                         cudaFuncAttributeMaxDynamicSharedMemorySize, SM_C2);
    cudaFuncSetAttribute((const void*)conv_gemm<128, 256, 5, 8, 1, 0>,
                         cudaFuncAttributeMaxDynamicSharedMemorySize, SM_C3);
    cudaFuncSetAttribute((const void*)conv_gemm<256, 512, 3, 16, 1, 0>,
                         cudaFuncAttributeMaxDynamicSharedMemorySize, SM_C4);
    cudaFuncSetAttribute((const void*)conv_gemm<512, 512, 3, 16, 0, 0>,
                         cudaFuncAttributeMaxDynamicSharedMemorySize, SM_C5);
    cudaFuncSetAttribute((const void*)conv_gemm<512, 256, 1, 16, 0, 1>,
                         cudaFuncAttributeMaxDynamicSharedMemorySize, SM_HD);
    cudaFuncSetAttribute((const void*)vq2_kernel,
                         cudaFuncAttributeMaxDynamicSharedMemorySize, V2_BYTES);

    prep_kernel<<<(N_PREP + 255) / 256, 256>>>(w2, w3, w4, w5, head_w, codebooks,
                                               w2T, w3T, w4T, w5T, hwT, cnm);
    gmax_kernel<<<8, 256>>>(cnm, cmx);

    conv1_kernel<<<dim3(32, 8), 128>>>(audio, w1, b1, x1);
    conv_gemm<64, 128, 5, 8, 1, 0><<<dim3(32, 1, 8), 256, SM_C2>>>(x1, w2T, b2, x2);
    conv_gemm<128, 256, 5, 8, 1, 0><<<dim3(32, 2, 8), 256, SM_C3>>>(x2, w3T, b3, x3);
    conv_gemm<256, 512, 3, 16, 1, 0><<<dim3(32, 4, 8), 256, SM_C4>>>(x3, w4T, b4, x4);
    conv_gemm<512, 512, 3, 16, 0, 0><<<dim3(32, 4, 8), 256, SM_C5>>>(x4, w5T, b5, x5);

    vq2_kernel<<<dim3(32, 8, 8), 256, V2_BYTES>>>(x5, codebooks, cnm, cmx, zqT,
                                                  out + OFF_A, part);
    conv_gemm<512, 256, 1, 16, 0, 1><<<dim3(32, 2, 8), 256, SM_HD>>>(zqT, hwT,
                                                                     head_b, out + OFF_B);
    loss_kernel<<<1, 256>>>(part, out);
}

// round 12
// speedup vs baseline: 1.1583x; 1.1583x over previous
#include <cuda_runtime.h>
#include <math.h>
#include <stdint.h>

// Problem constants
#define TLEN 4096
#define BSZ 8

typedef unsigned long long ull;

// Packed fp32x2 helpers
#define FMA2(acc, a, b) \
    asm("fma.rn.f32x2 %0, %1, %2, %3;" : "=l"(acc) : "l"(a), "l"(b), "l"(acc))
#define PACKB(d, s) \
    asm("mov.b64 %0, {%1, %1};" : "=l"(d) : "f"(s))
#define PACK2(d, lo, hi) \
    asm("mov.b64 %0, {%1, %2};" : "=l"(d) : "f"(lo), "f"(hi))
#define UNPACK2(lo, hi, s) \
    asm("mov.b64 {%0, %1}, %2;" : "=f"(lo), "=f"(hi) : "l"(s))

// cp.async primitives
__device__ __forceinline__ void cp4(uint32_t dst, const float* src, bool ok) {
    int sz = ok ? 4 : 0;
    asm volatile("cp.async.ca.shared.global [%0], [%1], 4, %2;"
                 :: "r"(dst), "l"(src), "r"(sz));
}
__device__ __forceinline__ void cp16(uint32_t dst, const void* src) {
    asm volatile("cp.async.cg.shared.global [%0], [%1], 16;"
                 :: "r"(dst), "l"(src));
}
#define CP_COMMIT() asm volatile("cp.async.commit_group;")
#define CP_WAIT(N) asm volatile("cp.async.wait_group %0;" :: "n"(N))

__device__ __forceinline__ int swz(int c) { return c ^ ((c >> 3) & 3); }
__device__ __forceinline__ int swzf(int p) { return (swz(p >> 2) << 2) | (p & 3); }

__device__ __forceinline__ uint32_t smem_u32(const void* p) {
    return (uint32_t)__cvta_generic_to_shared(p);
}

// ---------------- device scratch ----------------
__device__ float g_x1[BSZ * 64 * TLEN];
__device__ float g_x2[BSZ * 128 * TLEN];
__device__ float g_x3[BSZ * 256 * TLEN];
__device__ float g_x4[BSZ * 512 * TLEN];
__device__ float g_x5[BSZ * 512 * TLEN];
__device__ float g_w2T[64 * 5 * 128];
__device__ float g_w3T[128 * 5 * 256];
__device__ float g_w4T[256 * 3 * 512];
__device__ float g_w5T[512 * 3 * 512];
__device__ float g_hwT[512 * 256];                 // head weights [d][h*64+v]
__device__ float g_cnorm[8 * 1024];
__device__ float g_L[8 * 1024 * 256];              // code-logits table
__device__ float g_part[2048];

#define OFF_A 0
#define OFF_B (BSZ * 8 * TLEN)
#define OFF_L (OFF_B + BSZ * 4 * TLEN * 64)

// ---------------- prep (round-5 proven) ----------------
__device__ __forceinline__ void tr_seg(int local, const float* __restrict__ w,
                                       float* __restrict__ wT, int CIN, int COUT, int K) {
    int co = local % COUT;
    int j = (local / COUT) % K;
    int ci = local / (COUT * K);
    wT[local] = w[((size_t)co * CIN + ci) * K + j];
}
#define N_W2 (64 * 5 * 128)
#define N_W3 (128 * 5 * 256)
#define N_W4 (256 * 3 * 512)
#define N_W5 (512 * 3 * 512)
#define N_HW (512 * 256)
#define N_CN (8 * 1024)
#define N_PREP (N_W2 + N_W3 + N_W4 + N_W5 + N_HW + N_CN)

__global__ void prep_kernel(const float* __restrict__ w2, const float* __restrict__ w3,
                            const float* __restrict__ w4, const float* __restrict__ w5,
                            const float* __restrict__ hw, const float* __restrict__ cbk,
                            float* __restrict__ w2T, float* __restrict__ w3T,
                            float* __restrict__ w4T, float* __restrict__ w5T,
                            float* __restrict__ hwT, float* __restrict__ cnorm) {
    int i = blockIdx.x * 256 + threadIdx.x;
    if (i < N_W2) { tr_seg(i, w2, w2T, 64, 128, 5); return; }
    i -= N_W2;
    if (i < N_W3) { tr_seg(i, w3, w3T, 128, 256, 5); return; }
    i -= N_W3;
    if (i < N_W4) { tr_seg(i, w4, w4T, 256, 512, 3); return; }
    i -= N_W4;
    if (i < N_W5) { tr_seg(i, w5, w5T, 512, 512, 3); return; }
    i -= N_W5;
    if (i < N_HW) {
        int co = i % 256, d = i / 256;
        int h = co >> 6, v = co & 63;
        hwT[i] = hw[((size_t)h * 512 + d) * 64 + v];
        return;
    }
    i -= N_HW;
    if (i < N_CN) {
        const float* row = cbk + (size_t)i * 64;
        float s = 0.f;
#pragma unroll 8
        for (int d = 0; d < 64; d++) { float v = row[d]; s += v * v; }
        cnorm[i] = s;
    }
}

// ------- code-logits table: L[g][k][co] = sum_d cbk[g,k,d]*hwT[(g*64+d)*256+co]
__global__ __launch_bounds__(256)
void codelogits_kernel(const float* __restrict__ cbk, const float* __restrict__ hwT,
                       float* __restrict__ L) {
    extern __shared__ float smc[];
    float* sct = smc;            // [64][132] codes transposed (d, k)
    float* sw = smc + 64 * 132;  // [64][132] weights (d, co)
    const int k0 = blockIdx.x * 128;
    const int co0 = blockIdx.y * 128;
    const int g = blockIdx.z;
    const int tid = threadIdx.x;
    const int tx = tid & 15, ty = tid >> 4;
    const int kb = tx * 8, cb = ty * 8;

    for (int i = tid; i < 8192; i += 256) {
        int k = i >> 6, d = i & 63;
        sct[d * 132 + k] = cbk[((size_t)g * 1024 + k0 + k) * 64 + d];
    }
    for (int i = tid; i < 8192; i += 256) {
        int d = i >> 7, co = i & 127;
        sw[d * 132 + co] = hwT[((size_t)(g * 64 + d)) * 256 + co0 + co];
    }
    __syncthreads();

    float acc[8][8];
#pragma unroll
    for (int a = 0; a < 8; a++)
#pragma unroll
        for (int c = 0; c < 8; c++) acc[a][c] = 0.f;

#pragma unroll 4
    for (int d = 0; d < 64; d++) {
        float kk[8], ww[8];
        *(float4*)&kk[0] = *(const float4*)&sct[d * 132 + kb];
        *(float4*)&kk[4] = *(const float4*)&sct[d * 132 + kb + 4];
        *(float4*)&ww[0] = *(const float4*)&sw[d * 132 + cb];
        *(float4*)&ww[4] = *(const float4*)&sw[d * 132 + cb + 4];
#pragma unroll
        for (int a = 0; a < 8; a++)
#pragma unroll
            for (int c = 0; c < 8; c++) acc[a][c] = fmaf(kk[a], ww[c], acc[a][c]);
    }

#pragma unroll
    for (int a = 0; a < 8; a++) {
        float* base = L + ((size_t)g * 1024 + k0 + kb + a) * 256 + co0 + cb;
        *(float4*)base = *(float4*)&acc[a][0];
        *(float4*)(base + 4) = *(float4*)&acc[a][4];
    }
}

// ------- logits gather: b_logits[b,h,t,v] = sum_g L[g][idx[b,g,t]] + head_b ---
__global__ __launch_bounds__(256)
void glogits_kernel(const float* __restrict__ outA, const float* __restrict__ L,
                    const float* __restrict__ head_b, float* __restrict__ outB) {
    __shared__ int sidx[32][8];
    const int tid = threadIdx.x;
    const int tt0 = blockIdx.x * 32;
    {
        int tk = tid >> 3, g = tid & 7;
        int tt = tt0 + tk, b = tt >> 12, t = tt & 4095;
        sidx[tk][g] = (int)outA[((size_t)(b * 8 + g)) * TLEN + t];
    }
    __syncthreads();

    const int tok = tid >> 3, vc = tid & 7;
    const int tt = tt0 + tok, b = tt >> 12, t = tt & 4095;
    const int h = vc >> 1, v0 = (vc & 1) * 32;

    float acc[32];
    const float* bp = head_b + h * 64 + v0;
#pragma unroll
    for (int j = 0; j < 8; j++) *(float4*)&acc[j * 4] = *(const float4*)&bp[j * 4];

#pragma unroll
    for (int g = 0; g < 8; g++) {
        const float* Lr = L + ((size_t)(g << 10) + sidx[tok][g]) * 256 + vc * 32;
#pragma unroll
        for (int j = 0; j < 8; j++) {
            float4 lv = *(const float4*)&Lr[j * 4];
            acc[j * 4] += lv.x; acc[j * 4 + 1] += lv.y;
            acc[j * 4 + 2] += lv.z; acc[j * 4 + 3] += lv.w;
        }
    }

    float* op = outB + (((size_t)(b * 4 + h)) * TLEN + t) * 64 + v0;
#pragma unroll
    for (int j = 0; j < 8; j++) *(float4*)&op[j * 4] = *(const float4*)&acc[j * 4];
}

// ---------------- conv1 (round-5 proven) ----------------
__global__ void conv1_kernel(const float* __restrict__ audio, const float* __restrict__ w1,
                             const float* __restrict__ b1, float* __restrict__ y) {
    __shared__ float sx[134], sw[448], sbv[64];
    const int b = blockIdx.y, t0 = blockIdx.x * 128, tid = threadIdx.x;
    for (int i = tid; i < 134; i += 128) {
        int t = t0 - 6 + i;
        sx[i] = (t >= 0) ? audio[(size_t)b * TLEN + t] : 0.f;
    }
    for (int i = tid; i < 448; i += 128) sw[i] = w1[i];
    if (tid < 64) sbv[tid] = b1[tid];
    __syncthreads();
    float xv[7];
#pragma unroll
    for (int j = 0; j < 7; j++) xv[j] = sx[tid + j];
    for (int c = 0; c < 64; c++) {
        float acc = sbv[c];
#pragma unroll
        for (int j = 0; j < 7; j++) acc += sw[c * 7 + j] * xv[j];
        acc = acc > 0.f ? acc : expm1f(acc);
        y[((size_t)b * 64 + c) * TLEN + t0 + tid] = acc;
    }
}

// ---- conv-as-GEMM, round-5 proven (f32x2, 3-stage cp.async) ----
template <int CIN, int COUT, int K, int CI_CHUNK, int ELU>
__global__ __launch_bounds__(256, 2)
void conv_gemm(const float* __restrict__ x, const float* __restrict__ wT,
               const float* __restrict__ bias, float* __restrict__ y) {
    constexpr int XROW = 136;
    constexpr int NX = 8 + K - 1;
    constexpr int NXF4 = (NX + 3) / 4;
    constexpr int XS_FL = CI_CHUNK * XROW;
    constexpr int WS_FL = CI_CHUNK * K * 128;
    constexpr int STG_FL = XS_FL + WS_FL;
    constexpr int NCHUNK = CIN / CI_CHUNK;

    extern __shared__ float smem[];
    const uint32_t sb = smem_u32(smem);
    const int b = blockIdx.z, t0 = blockIdx.x * 128, co0 = blockIdx.y * 128;
    const int tid = threadIdx.x;
    const int tx = tid & 15, ty = tid >> 4;
    const int tb = tx * 8, cb = ty * 8;

    auto load_chunk = [&](int c, int st) {
        const int ci0 = c * CI_CHUNK;
        uint32_t xbB = sb + (uint32_t)(st * STG_FL) * 4u;
        for (int i = tid; i < XS_FL; i += 256) {
            int cc = i / XROW, p = i % XROW;
            int t = t0 - (K - 1) + p;
            bool ok = (t >= 0) && (t < TLEN);
            const float* src = x + ((size_t)b * CIN + ci0 + cc) * TLEN + (ok ? t : 0);
            cp4(xbB + (uint32_t)(cc * XROW + swzf(p)) * 4u, src, ok);
        }
        uint32_t wbB = xbB + (uint32_t)XS_FL * 4u;
        for (int i4 = tid * 4; i4 < WS_FL; i4 += 1024) {
            int cc = i4 / (K * 128);
            int rem = i4 % (K * 128);
            int j = rem / 128, co = rem % 128;
            cp16(wbB + (uint32_t)i4 * 4u,
                 wT + ((size_t)(ci0 + cc) * K + j) * COUT + co0 + co);
        }
        CP_COMMIT();
    };

    load_chunk(0, 0);
    if (NCHUNK > 1) load_chunk(1, 1);

    ull acc2[4][8];
#pragma unroll
    for (int rp = 0; rp < 4; rp++) {
        ull bb2;
        PACK2(bb2, bias[co0 + cb + 2 * rp], bias[co0 + cb + 2 * rp + 1]);
#pragma unroll
        for (int lt = 0; lt < 8; lt++) acc2[rp][lt] = bb2;
    }

    int st = 0;
#pragma unroll 1
    for (int c = 0; c < NCHUNK; c++) {
        if (c + 1 < NCHUNK) { CP_WAIT(1); } else { CP_WAIT(0); }
        __syncthreads();
        if (c + 2 < NCHUNK) {
            int st2 = st + 2; if (st2 >= 3) st2 -= 3;
            load_chunk(c + 2, st2);
        }
        const float* xsb = smem + st * STG_FL;
        const float* wsb = xsb + XS_FL;
#pragma unroll 1
        for (int cc = 0; cc < CI_CHUNK; cc++) {
            const float* xrow = xsb + cc * XROW;
            float xv[NXF4 * 4];
#pragma unroll
            for (int q = 0; q < NXF4; q++)
                *(float4*)&xv[q * 4] = *(const float4*)&xrow[swz(tx * 2 + q) << 2];
            ull xb[NX];
#pragma unroll
            for (int p = 0; p < NX; p++) PACKB(xb[p], xv[p]);
#pragma unroll
            for (int j = 0; j < K; j++) {
                const float* wrow = wsb + (cc * K + j) * 128 + cb;
                ulonglong2 w01 = *(const ulonglong2*)&wrow[0];
                ulonglong2 w23 = *(const ulonglong2*)&wrow[4];
                ull wp[4] = {w01.x, w01.y, w23.x, w23.y};
#pragma unroll
                for (int rp = 0; rp < 4; rp++)
#pragma unroll
                    for (int lt = 0; lt < 8; lt++)
                        FMA2(acc2[rp][lt], wp[rp], xb[lt + j]);
            }
        }
        if (++st == 3) st = 0;
    }

    float accs[8][8];
#pragma unroll
    for (int rp = 0; rp < 4; rp++)
#pragma unroll
        for (int lt = 0; lt < 8; lt++)
            UNPACK2(accs[2 * rp][lt], accs[2 * rp + 1][lt], acc2[rp][lt]);

#pragma unroll
    for (int r = 0; r < 8; r++) {
        float o[8];
#pragma unroll
        for (int lt = 0; lt < 8; lt++) {
            float a = accs[r][lt];
            if (ELU) a = a > 0.f ? a : expm1f(a);
            o[lt] = a;
        }
        float* base = &y[((size_t)b * COUT + co0 + cb + r) * TLEN + t0 + tb];
        *(float4*)base = *(float4*)&o[0];
        *(float4*)(base + 4) = *(float4*)&o[4];
    }
}

// ---------------- VQ (round-5 proven, minus z_q store) ----------------
#define VQ_ZT 0
#define VQ_CB0 8192
#define VQ_CB1 (8192 + 8448)
#define VQ_CNORM (8192 + 16896)
#define VQ_ZN (VQ_CNORM + 1024)
#define VQ_BI (VQ_ZN + 128)
#define VQ_FLOATS (VQ_BI + 128)
#define VQ_BYTES (VQ_FLOATS * 4)
#define VQ_RV VQ_CB0
#define VQ_RI (VQ_CB0 + 2048)
#define VQ_LS VQ_CNORM

__global__ __launch_bounds__(256, 2)
void vq_kernel(const float* __restrict__ x5, const float* __restrict__ cbk,
               const float* __restrict__ cnormG,
               float* __restrict__ out_a, float* __restrict__ partial) {
    extern __shared__ float smem[];
    const uint32_t sb = smem_u32(smem);
    float* ztT = smem + VQ_ZT;
    float* cnormS = smem + VQ_CNORM;
    float* znorm = smem + VQ_ZN;
    int* besti = (int*)(smem + VQ_BI);
    float* redv = smem + VQ_RV;
    int* redi = (int*)(smem + VQ_RI);
    float* lscr = smem + VQ_LS;

    const int b = blockIdx.z, g = blockIdx.y;
    const int t0 = blockIdx.x * 128;
    const int tid = threadIdx.x;
    const int tx = tid & 15, ty = tid >> 4;
    const int trow = tx * 8, cbase = ty * 8;

    for (int i = tid; i < 8192; i += 256) {
        int d = i >> 7, lt = i & 127;
        cp4(sb + (uint32_t)(VQ_ZT + d * 128 + swzf(lt)) * 4u,
            x5 + (((size_t)b * 512) + (g << 6) + d) * TLEN + t0 + lt, true);
    }
    cp16(sb + (uint32_t)(VQ_CNORM + tid * 4) * 4u, cnormG + g * 1024 + tid * 4);
    for (int i = tid; i < 8192; i += 256) {
        int kk = i >> 6, d = i & 63;
        cp4(sb + (uint32_t)(VQ_CB0 + d * 132 + kk) * 4u,
            cbk + ((size_t)g * 1024 + kk) * 64 + d, true);
    }
    CP_COMMIT();

    float zn[8], bv[8];
    int bi8[8];
#pragma unroll
    for (int a = 0; a < 8; a++) { bv[a] = 3.4e38f; bi8[a] = 0; }

#pragma unroll 1
    for (int c = 0; c < 8; c++) {
        const int k0 = c << 7;
        if (c + 1 < 8) {
            const int koff = (c + 1) << 7;
            uint32_t cbB = sb + (uint32_t)(((c + 1) & 1) ? VQ_CB1 : VQ_CB0) * 4u;
            for (int i = tid; i < 8192; i += 256) {
                int kk = i >> 6, d = i & 63;
                cp4(cbB + (uint32_t)(d * 132 + kk) * 4u,
                    cbk + ((size_t)g * 1024 + koff + kk) * 64 + d, true);
            }
            CP_COMMIT();
            CP_WAIT(1);
        } else {
            CP_WAIT(0);
        }
        __syncthreads();

        if (c == 0) {
            if (tid < 128) {
                float s = 0.f;
                int off = swzf(tid);
#pragma unroll 8
                for (int d = 0; d < 64; d++) { float v = ztT[d * 128 + off]; s += v * v; }
                znorm[tid] = s;
            }
            __syncthreads();
#pragma unroll
            for (int a = 0; a < 8; a++) zn[a] = znorm[trow + a];
        }

        const float* ct = smem + ((c & 1) ? VQ_CB1 : VQ_CB0);
        ull acc2[8][4];
#pragma unroll
        for (int a = 0; a < 8; a++)
#pragma unroll
            for (int q = 0; q < 4; q++) acc2[a][q] = 0ull;

#pragma unroll 4
        for (int d = 0; d < 64; d++) {
            float zz[8];
            *(float4*)&zz[0] = *(const float4*)&ztT[d * 128 + (swz(tx * 2) << 2)];
            *(float4*)&zz[4] = *(const float4*)&ztT[d * 128 + (swz(tx * 2 + 1) << 2)];
            ull zb[8];
#pragma unroll
            for (int a = 0; a < 8; a++) PACKB(zb[a], zz[a]);
            ulonglong2 c01 = *(const ulonglong2*)&ct[d * 132 + cbase];
            ulonglong2 c23 = *(const ulonglong2*)&ct[d * 132 + cbase + 4];
            ull cp_[4] = {c01.x, c01.y, c23.x, c23.y};
#pragma unroll
            for (int a = 0; a < 8; a++)
#pragma unroll
                for (int q = 0; q < 4; q++)
                    FMA2(acc2[a][q], zb[a], cp_[q]);
        }

        float accs[8][8];
#pragma unroll
        for (int a = 0; a < 8; a++)
#pragma unroll
            for (int q = 0; q < 4; q++)
                UNPACK2(accs[a][2 * q], accs[a][2 * q + 1], acc2[a][q]);

        float cn[8];
#pragma unroll
        for (int cc = 0; cc < 8; cc++) cn[cc] = cnormS[k0 + cbase + cc];
#pragma unroll
        for (int a = 0; a < 8; a++) {
#pragma unroll
            for (int cc = 0; cc < 8; cc++) {
                float dist = zn[a] + cn[cc] - 2.f * accs[a][cc];
                int idx = k0 + cbase + cc;
                if (dist < bv[a]) { bv[a] = dist; bi8[a] = idx; }
            }
        }
        __syncthreads();
    }

#pragma unroll
    for (int a = 0; a < 8; a++) {
        int tok = trow + a;
        redv[tok * 16 + ty] = bv[a];
        redi[tok * 16 + ty] = bi8[a];
    }
    __syncthreads();
    if (tid < 128) {
        float best = redv[tid * 16];
        int bidx = redi[tid * 16];
#pragma unroll
        for (int s = 1; s < 16; s++) {
            float v = redv[tid * 16 + s];
            int ii = redi[tid * 16 + s];
            if (v < best || (v == best && ii < bidx)) { best = v; bidx = ii; }
        }
        besti[tid] = bidx;
        out_a[((size_t)b * 8 + g) * TLEN + t0 + tid] = (float)bidx;
    }
    __syncthreads();

    // exact loss (no z_q staging/store needed anymore)
    float ls = 0.f;
    for (int i = tid; i < 64 * 128; i += 256) {
        int d = i & 63, lt = i >> 6;
        float qv = cbk[((size_t)g * 1024 + besti[lt]) * 64 + d];
        float df = qv - ztT[d * 128 + swzf(lt)];
        ls += df * df;
    }
    lscr[tid] = ls;
    __syncthreads();
    for (int s = 128; s > 0; s >>= 1) {
        if (tid < s) lscr[tid] += lscr[tid + s];
        __syncthreads();
    }
    if (tid == 0)
        partial[((size_t)b * 8 + g) * 32 + blockIdx.x] = lscr[0];
}

__global__ void loss_kernel(const float* __restrict__ partial, float* __restrict__ out) {
    __shared__ float s[256];
    int tid = threadIdx.x;
    float v = 0.f;
    for (int i = tid; i < 2048; i += 256) v += partial[i];
    s[tid] = v;
    __syncthreads();
    for (int k = 128; k > 0; k >>= 1) {
        if (tid < k) s[tid] += s[tid + k];
        __syncthreads();
    }
    if (tid == 0) out[OFF_L] = s[0] * (1.f / (8.f * 4096.f * 64.f));
}

// ---------------- launch ----------------
extern "C" void kernel_launch(void* const* d_in, const int* in_sizes, int n_in,
                              void* d_out, int out_size) {
    const float* audio = (const float*)d_in[0];
    const float* w1 = (const float*)d_in[1];
    const float* b1 = (const float*)d_in[2];
    const float* w2 = (const float*)d_in[3];
    const float* b2 = (const float*)d_in[4];
    const float* w3 = (const float*)d_in[5];
    const float* b3 = (const float*)d_in[6];
    const float* w4 = (const float*)d_in[7];
    const float* b4 = (const float*)d_in[8];
    const float* w5 = (const float*)d_in[9];
    const float* b5 = (const float*)d_in[10];
    const float* codebooks = (const float*)d_in[11];
    const float* head_w = (const float*)d_in[12];
    const float* head_b = (const float*)d_in[13];
    float* out = (float*)d_out;

    float *x1, *x2, *x3, *x4, *x5, *w2T, *w3T, *w4T, *w5T, *hwT, *cnm, *Lt, *part;
    cudaGetSymbolAddress((void**)&x1, g_x1);
    cudaGetSymbolAddress((void**)&x2, g_x2);
    cudaGetSymbolAddress((void**)&x3, g_x3);
    cudaGetSymbolAddress((void**)&x4, g_x4);
    cudaGetSymbolAddress((void**)&x5, g_x5);
    cudaGetSymbolAddress((void**)&w2T, g_w2T);
    cudaGetSymbolAddress((void**)&w3T, g_w3T);
    cudaGetSymbolAddress((void**)&w4T, g_w4T);
    cudaGetSymbolAddress((void**)&w5T, g_w5T);
    cudaGetSymbolAddress((void**)&hwT, g_hwT);
    cudaGetSymbolAddress((void**)&cnm, g_cnorm);
    cudaGetSymbolAddress((void**)&Lt, g_L);
    cudaGetSymbolAddress((void**)&part, g_part);

    const int SM_C2 = (3 * (8 * 136 + 8 * 5 * 128)) * 4;
    const int SM_C3 = SM_C2;
    const int SM_C4 = (3 * (16 * 136 + 16 * 3 * 128)) * 4;
    const int SM_C5 = SM_C4;
    const int SM_CL = (2 * 64 * 132) * 4;          // 67584

    cudaFuncSetAttribute((const void*)conv_gemm<64, 128, 5, 8, 1>,
                         cudaFuncAttributeMaxDynamicSharedMemorySize, SM_C2);
    cudaFuncSetAttribute((const void*)conv_gemm<128, 256, 5, 8, 1>,
                         cudaFuncAttributeMaxDynamicSharedMemorySize, SM_C3);
    cudaFuncSetAttribute((const void*)conv_gemm<256, 512, 3, 16, 1>,
                         cudaFuncAttributeMaxDynamicSharedMemorySize, SM_C4);
    cudaFuncSetAttribute((const void*)conv_gemm<512, 512, 3, 16, 0>,
                         cudaFuncAttributeMaxDynamicSharedMemorySize, SM_C5);
    cudaFuncSetAttribute((const void*)codelogits_kernel,
                         cudaFuncAttributeMaxDynamicSharedMemorySize, SM_CL);
    cudaFuncSetAttribute((const void*)vq_kernel,
                         cudaFuncAttributeMaxDynamicSharedMemorySize, VQ_BYTES);

    prep_kernel<<<(N_PREP + 255) / 256, 256>>>(w2, w3, w4, w5, head_w, codebooks,
                                               w2T, w3T, w4T, w5T, hwT, cnm);
    codelogits_kernel<<<dim3(8, 2, 8), 256, SM_CL>>>(codebooks, hwT, Lt);

    conv1_kernel<<<dim3(32, 8), 128>>>(audio, w1, b1, x1);
    conv_gemm<64, 128, 5, 8, 1><<<dim3(32, 1, 8), 256, SM_C2>>>(x1, w2T, b2, x2);
    conv_gemm<128, 256, 5, 8, 1><<<dim3(32, 2, 8), 256, SM_C3>>>(x2, w3T, b3, x3);
    conv_gemm<256, 512, 3, 16, 1><<<dim3(32, 4, 8), 256, SM_C4>>>(x3, w4T, b4, x4);
    conv_gemm<512, 512, 3, 16, 0><<<dim3(32, 4, 8), 256, SM_C5>>>(x4, w5T, b5, x5);

    vq_kernel<<<dim3(32, 8, 8), 256, VQ_BYTES>>>(x5, codebooks, cnm,
                                                 out + OFF_A, part);
    glogits_kernel<<<1024, 256>>>(out + OFF_A, Lt, head_b, out + OFF_B);
    loss_kernel<<<1, 256>>>(part, out);
}

// round 13
// speedup vs baseline: 1.1718x; 1.0117x over previous
#include <cuda_runtime.h>
#include <math.h>
#include <stdint.h>

// Problem constants
#define TLEN 4096
#define BSZ 8

typedef unsigned long long ull;

// Packed fp32x2 helpers
#define FMA2(acc, a, b) \
    asm("fma.rn.f32x2 %0, %1, %2, %3;" : "=l"(acc) : "l"(a), "l"(b), "l"(acc))
#define PACKB(d, s) \
    asm("mov.b64 %0, {%1, %1};" : "=l"(d) : "f"(s))
#define PACK2(d, lo, hi) \
    asm("mov.b64 %0, {%1, %2};" : "=l"(d) : "f"(lo), "f"(hi))
#define UNPACK2(lo, hi, s) \
    asm("mov.b64 {%0, %1}, %2;" : "=f"(lo), "=f"(hi) : "l"(s))

// cp.async primitives
__device__ __forceinline__ void cp4(uint32_t dst, const float* src, bool ok) {
    int sz = ok ? 4 : 0;
    asm volatile("cp.async.ca.shared.global [%0], [%1], 4, %2;"
                 :: "r"(dst), "l"(src), "r"(sz));
}
__device__ __forceinline__ void cp16(uint32_t dst, const void* src) {
    asm volatile("cp.async.cg.shared.global [%0], [%1], 16;"
                 :: "r"(dst), "l"(src));
}
#define CP_COMMIT() asm volatile("cp.async.commit_group;")
#define CP_WAIT(N) asm volatile("cp.async.wait_group %0;" :: "n"(N))

__device__ __forceinline__ int swz(int c) { return c ^ ((c >> 3) & 3); }
__device__ __forceinline__ int swzf(int p) { return (swz(p >> 2) << 2) | (p & 3); }

__device__ __forceinline__ uint32_t smem_u32(const void* p) {
    return (uint32_t)__cvta_generic_to_shared(p);
}

// ---------------- device scratch ----------------
__device__ float g_x2[BSZ * 128 * TLEN];
__device__ float g_x3[BSZ * 256 * TLEN];
__device__ float g_x4[BSZ * 512 * TLEN];
__device__ float g_x5[BSZ * 512 * TLEN];
__device__ float g_w2T[64 * 5 * 128];
__device__ float g_w3T[128 * 5 * 256];
__device__ float g_w4T[256 * 3 * 512];
__device__ float g_w5T[512 * 3 * 512];
__device__ float g_hwT[512 * 256];                 // head weights [d][h*64+v]
__device__ float g_cnorm[8 * 1024];
__device__ float g_L[8 * 1024 * 256];              // code-logits table
__device__ float g_part[2048];

#define OFF_A 0
#define OFF_B (BSZ * 8 * TLEN)
#define OFF_L (OFF_B + BSZ * 4 * TLEN * 64)

// ---------------- prep (proven) ----------------
__device__ __forceinline__ void tr_seg(int local, const float* __restrict__ w,
                                       float* __restrict__ wT, int CIN, int COUT, int K) {
    int co = local % COUT;
    int j = (local / COUT) % K;
    int ci = local / (COUT * K);
    wT[local] = w[((size_t)co * CIN + ci) * K + j];
}
#define N_W2 (64 * 5 * 128)
#define N_W3 (128 * 5 * 256)
#define N_W4 (256 * 3 * 512)
#define N_W5 (512 * 3 * 512)
#define N_HW (512 * 256)
#define N_CN (8 * 1024)
#define N_PREP (N_W2 + N_W3 + N_W4 + N_W5 + N_HW + N_CN)

__global__ void prep_kernel(const float* __restrict__ w2, const float* __restrict__ w3,
                            const float* __restrict__ w4, const float* __restrict__ w5,
                            const float* __restrict__ hw, const float* __restrict__ cbk,
                            float* __restrict__ w2T, float* __restrict__ w3T,
                            float* __restrict__ w4T, float* __restrict__ w5T,
                            float* __restrict__ hwT, float* __restrict__ cnorm) {
    int i = blockIdx.x * 256 + threadIdx.x;
    if (i < N_W2) { tr_seg(i, w2, w2T, 64, 128, 5); return; }
    i -= N_W2;
    if (i < N_W3) { tr_seg(i, w3, w3T, 128, 256, 5); return; }
    i -= N_W3;
    if (i < N_W4) { tr_seg(i, w4, w4T, 256, 512, 3); return; }
    i -= N_W4;
    if (i < N_W5) { tr_seg(i, w5, w5T, 512, 512, 3); return; }
    i -= N_W5;
    if (i < N_HW) {
        int co = i % 256, d = i / 256;
        int h = co >> 6, v = co & 63;
        hwT[i] = hw[((size_t)h * 512 + d) * 64 + v];
        return;
    }
    i -= N_HW;
    if (i < N_CN) {
        const float* row = cbk + (size_t)i * 64;
        float s = 0.f;
#pragma unroll 8
        for (int d = 0; d < 64; d++) { float v = row[d]; s += v * v; }
        cnorm[i] = s;
    }
}

// ------- code-logits table: L[g][k][co] = sum_d cbk[g,k,d]*hwT[(g*64+d)*256+co]
__global__ __launch_bounds__(256)
void codelogits_kernel(const float* __restrict__ cbk, const float* __restrict__ hwT,
                       float* __restrict__ L) {
    extern __shared__ float smc[];
    float* sct = smc;            // [64][132] codes transposed (d, k)
    float* sw = smc + 64 * 132;  // [64][132] weights (d, co)
    const int k0 = blockIdx.x * 128;
    const int co0 = blockIdx.y * 128;
    const int g = blockIdx.z;
    const int tid = threadIdx.x;
    const int tx = tid & 15, ty = tid >> 4;
    const int kb = tx * 8, cb = ty * 8;

    for (int i = tid; i < 8192; i += 256) {
        int k = i >> 6, d = i & 63;
        sct[d * 132 + k] = cbk[((size_t)g * 1024 + k0 + k) * 64 + d];
    }
    for (int i = tid; i < 8192; i += 256) {
        int d = i >> 7, co = i & 127;
        sw[d * 132 + co] = hwT[((size_t)(g * 64 + d)) * 256 + co0 + co];
    }
    __syncthreads();

    float acc[8][8];
#pragma unroll
    for (int a = 0; a < 8; a++)
#pragma unroll
        for (int c = 0; c < 8; c++) acc[a][c] = 0.f;

#pragma unroll 4
    for (int d = 0; d < 64; d++) {
        float kk[8], ww[8];
        *(float4*)&kk[0] = *(const float4*)&sct[d * 132 + kb];
        *(float4*)&kk[4] = *(const float4*)&sct[d * 132 + kb + 4];
        *(float4*)&ww[0] = *(const float4*)&sw[d * 132 + cb];
        *(float4*)&ww[4] = *(const float4*)&sw[d * 132 + cb + 4];
#pragma unroll
        for (int a = 0; a < 8; a++)
#pragma unroll
            for (int c = 0; c < 8; c++) acc[a][c] = fmaf(kk[a], ww[c], acc[a][c]);
    }

#pragma unroll
    for (int a = 0; a < 8; a++) {
        float* base = L + ((size_t)g * 1024 + k0 + kb + a) * 256 + co0 + cb;
        *(float4*)base = *(float4*)&acc[a][0];
        *(float4*)(base + 4) = *(float4*)&acc[a][4];
    }
}

// ------- logits gather (+ fused final loss in trailing block) ---------------
__global__ __launch_bounds__(256)
void glogits_kernel(const float* __restrict__ outA, const float* __restrict__ L,
                    const float* __restrict__ head_b, float* __restrict__ outB,
                    const float* __restrict__ partial, float* __restrict__ outLoss) {
    const int tid = threadIdx.x;

    if (blockIdx.x == 1024) {        // fused deterministic loss reduction
        __shared__ float s[256];
        float v = 0.f;
        for (int i = tid; i < 2048; i += 256) v += partial[i];
        s[tid] = v;
        __syncthreads();
        for (int k = 128; k > 0; k >>= 1) {
            if (tid < k) s[tid] += s[tid + k];
            __syncthreads();
        }
        if (tid == 0) outLoss[0] = s[0] * (1.f / (8.f * 4096.f * 64.f));
        return;
    }

    __shared__ int sidx[32][8];
    const int tt0 = blockIdx.x * 32;
    {
        int tk = tid >> 3, g = tid & 7;
        int tt = tt0 + tk, b = tt >> 12, t = tt & 4095;
        sidx[tk][g] = (int)outA[((size_t)(b * 8 + g)) * TLEN + t];
    }
    __syncthreads();

    const int tok = tid >> 3, vc = tid & 7;
    const int tt = tt0 + tok, b = tt >> 12, t = tt & 4095;
    const int h = vc >> 1, v0 = (vc & 1) * 32;

    float acc[32];
    const float* bp = head_b + h * 64 + v0;
#pragma unroll
    for (int j = 0; j < 8; j++) *(float4*)&acc[j * 4] = *(const float4*)&bp[j * 4];

#pragma unroll
    for (int g = 0; g < 8; g++) {
        const float* Lr = L + ((size_t)(g << 10) + sidx[tok][g]) * 256 + vc * 32;
#pragma unroll
        for (int j = 0; j < 8; j++) {
            float4 lv = *(const float4*)&Lr[j * 4];
            acc[j * 4] += lv.x; acc[j * 4 + 1] += lv.y;
            acc[j * 4 + 2] += lv.z; acc[j * 4 + 3] += lv.w;
        }
    }

    float* op = outB + (((size_t)(b * 4 + h)) * TLEN + t) * 64 + v0;
#pragma unroll
    for (int j = 0; j < 8; j++) *(float4*)&op[j * 4] = *(const float4*)&acc[j * 4];
}

// ------ conv1+conv2 fused: compute x1 tile in smem, then w-pipelined GEMM ---
// x1 math bitwise-identical to the old conv1_kernel (bias-first, ascending j,
// ELU, t<0 -> 0), so downstream values are unchanged.
#define C12_XROW 136
#define C12_AUD 0                              // 144 floats (138 used)
#define C12_W1 144                             // 448
#define C12_B1 (144 + 448)                     // 64
#define C12_X1 (144 + 448 + 64)                // 64*136 = 8704
#define C12_WS (C12_X1 + 64 * C12_XROW)        // 3 stages x 5120
#define C12_FLOATS (C12_WS + 3 * 5120)         // 24816
#define C12_BYTES (C12_FLOATS * 4)             // 99264

__global__ __launch_bounds__(256, 2)
void conv12_kernel(const float* __restrict__ audio, const float* __restrict__ w1,
                   const float* __restrict__ b1, const float* __restrict__ wT,
                   const float* __restrict__ bias, float* __restrict__ y) {
    constexpr int K = 5, CIN = 64, COUT = 128, CI_CHUNK = 8;
    constexpr int NX = 12, NXF4 = 3;
    constexpr int WS_FL = CI_CHUNK * K * 128;   // 5120
    constexpr int NCHUNK = CIN / CI_CHUNK;      // 8

    extern __shared__ float smem[];
    const uint32_t sb = smem_u32(smem);
    float* audio_s = smem + C12_AUD;
    float* w1s = smem + C12_W1;
    float* b1s = smem + C12_B1;
    float* x1s = smem + C12_X1;

    const int b = blockIdx.z, t0 = blockIdx.x * 128;
    const int tid = threadIdx.x;
    const int tx = tid & 15, ty = tid >> 4;
    const int tb = tx * 8, cb = ty * 8;

    auto loadW = [&](int c, int st) {
        uint32_t wbB = sb + (uint32_t)(C12_WS + st * WS_FL) * 4u;
        const int ci0 = c * CI_CHUNK;
        for (int i4 = tid * 4; i4 < WS_FL; i4 += 1024) {
            int cc = i4 / (K * 128);
            int rem = i4 % (K * 128);
            int j = rem / 128, co = rem % 128;
            cp16(wbB + (uint32_t)i4 * 4u,
                 wT + ((size_t)(ci0 + cc) * K + j) * COUT + co);
        }
        CP_COMMIT();
    };

    // group A: audio window [t0-10, t0+127], w1, b1
    for (int i = tid; i < 138; i += 256) {
        int t = t0 - 10 + i;
        cp4(sb + (uint32_t)(C12_AUD + i) * 4u,
            audio + (size_t)b * TLEN + (t >= 0 ? t : 0), t >= 0);
    }
    for (int i4 = tid * 4; i4 < 448; i4 += 1024)
        cp16(sb + (uint32_t)(C12_W1 + i4) * 4u, w1 + i4);
    if (tid < 16)
        cp16(sb + (uint32_t)(C12_B1 + tid * 4) * 4u, b1 + tid * 4);
    CP_COMMIT();
    loadW(0, 0);
    loadW(1, 1);

    CP_WAIT(2);            // group A (audio/w1/b1) complete
    __syncthreads();

    // compute x1 tile: positions p in [0,132) -> t = t0-4+p (conv2 halo = 4)
    for (int i = tid; i < 64 * 132; i += 256) {
        int ch = i / 132, p = i % 132;
        int t = t0 - 4 + p;
        float v = 0.f;
        if (t >= 0) {
            float acc = b1s[ch];
#pragma unroll
            for (int j = 0; j < 7; j++) acc += w1s[ch * 7 + j] * audio_s[p + j];
            v = acc > 0.f ? acc : expm1f(acc);
        }
        x1s[ch * C12_XROW + swzf(p)] = v;
    }
    __syncthreads();

    ull acc2[4][8];
#pragma unroll
    for (int rp = 0; rp < 4; rp++) {
        ull bb2;
        PACK2(bb2, bias[cb + 2 * rp], bias[cb + 2 * rp + 1]);
#pragma unroll
        for (int lt = 0; lt < 8; lt++) acc2[rp][lt] = bb2;
    }

    int st = 0;
#pragma unroll 1
    for (int c = 0; c < NCHUNK; c++) {
        if (c + 1 < NCHUNK) { CP_WAIT(1); } else { CP_WAIT(0); }
        __syncthreads();
        if (c + 2 < NCHUNK) {
            int st2 = st + 2; if (st2 >= 3) st2 -= 3;
            loadW(c + 2, st2);
        }
        const float* wsb = smem + C12_WS + st * WS_FL;
        const float* xbase = x1s + c * CI_CHUNK * C12_XROW;
#pragma unroll 1
        for (int cc = 0; cc < CI_CHUNK; cc++) {
            const float* xrow = xbase + cc * C12_XROW;
            float xv[NXF4 * 4];
#pragma unroll
            for (int q = 0; q < NXF4; q++)
                *(float4*)&xv[q * 4] = *(const float4*)&xrow[swz(tx * 2 + q) << 2];
            ull xb[NX];
#pragma unroll
            for (int p = 0; p < NX; p++) PACKB(xb[p], xv[p]);
#pragma unroll
            for (int j = 0; j < K; j++) {
                const float* wrow = wsb + (cc * K + j) * 128 + cb;
                ulonglong2 w01 = *(const ulonglong2*)&wrow[0];
                ulonglong2 w23 = *(const ulonglong2*)&wrow[4];
                ull wp[4] = {w01.x, w01.y, w23.x, w23.y};
#pragma unroll
                for (int rp = 0; rp < 4; rp++)
#pragma unroll
                    for (int lt = 0; lt < 8; lt++)
                        FMA2(acc2[rp][lt], wp[rp], xb[lt + j]);
            }
        }
        if (++st == 3) st = 0;
    }

    float accs[8][8];
#pragma unroll
    for (int rp = 0; rp < 4; rp++)
#pragma unroll
        for (int lt = 0; lt < 8; lt++)
            UNPACK2(accs[2 * rp][lt], accs[2 * rp + 1][lt], acc2[rp][lt]);

#pragma unroll
    for (int r = 0; r < 8; r++) {
        float o[8];
#pragma unroll
        for (int lt = 0; lt < 8; lt++) {
            float a = accs[r][lt];
            o[lt] = a > 0.f ? a : expm1f(a);   // ELU
        }
        float* base = &y[((size_t)b * COUT + cb + r) * TLEN + t0 + tb];
        *(float4*)base = *(float4*)&o[0];
        *(float4*)(base + 4) = *(float4*)&o[4];
    }
}

// ---- conv-as-GEMM, proven (f32x2, 3-stage cp.async) — conv3/4/5 ----
template <int CIN, int COUT, int K, int CI_CHUNK, int ELU>
__global__ __launch_bounds__(256, 2)
void conv_gemm(const float* __restrict__ x, const float* __restrict__ wT,
               const float* __restrict__ bias, float* __restrict__ y) {
    constexpr int XROW = 136;
    constexpr int NX = 8 + K - 1;
    constexpr int NXF4 = (NX + 3) / 4;
    constexpr int XS_FL = CI_CHUNK * XROW;
    constexpr int WS_FL = CI_CHUNK * K * 128;
    constexpr int STG_FL = XS_FL + WS_FL;
    constexpr int NCHUNK = CIN / CI_CHUNK;

    extern __shared__ float smem[];
    const uint32_t sb = smem_u32(smem);
    const int b = blockIdx.z, t0 = blockIdx.x * 128, co0 = blockIdx.y * 128;
    const int tid = threadIdx.x;
    const int tx = tid & 15, ty = tid >> 4;
    const int tb = tx * 8, cb = ty * 8;

    auto load_chunk = [&](int c, int st) {
        const int ci0 = c * CI_CHUNK;
        uint32_t xbB = sb + (uint32_t)(st * STG_FL) * 4u;
        for (int i = tid; i < XS_FL; i += 256) {
            int cc = i / XROW, p = i % XROW;
            int t = t0 - (K - 1) + p;
            bool ok = (t >= 0) && (t < TLEN);
            const float* src = x + ((size_t)b * CIN + ci0 + cc) * TLEN + (ok ? t : 0);
            cp4(xbB + (uint32_t)(cc * XROW + swzf(p)) * 4u, src, ok);
        }
        uint32_t wbB = xbB + (uint32_t)XS_FL * 4u;
        for (int i4 = tid * 4; i4 < WS_FL; i4 += 1024) {
            int cc = i4 / (K * 128);
            int rem = i4 % (K * 128);
            int j = rem / 128, co = rem % 128;
            cp16(wbB + (uint32_t)i4 * 4u,
                 wT + ((size_t)(ci0 + cc) * K + j) * COUT + co0 + co);
        }
        CP_COMMIT();
    };

    load_chunk(0, 0);
    if (NCHUNK > 1) load_chunk(1, 1);

    ull acc2[4][8];
#pragma unroll
    for (int rp = 0; rp < 4; rp++) {
        ull bb2;
        PACK2(bb2, bias[co0 + cb + 2 * rp], bias[co0 + cb + 2 * rp + 1]);
#pragma unroll
        for (int lt = 0; lt < 8; lt++) acc2[rp][lt] = bb2;
    }

    int st = 0;
#pragma unroll 1
    for (int c = 0; c < NCHUNK; c++) {
        if (c + 1 < NCHUNK) { CP_WAIT(1); } else { CP_WAIT(0); }
        __syncthreads();
        if (c + 2 < NCHUNK) {
            int st2 = st + 2; if (st2 >= 3) st2 -= 3;
            load_chunk(c + 2, st2);
        }
        const float* xsb = smem + st * STG_FL;
        const float* wsb = xsb + XS_FL;
#pragma unroll 1
        for (int cc = 0; cc < CI_CHUNK; cc++) {
            const float* xrow = xsb + cc * XROW;
            float xv[NXF4 * 4];
#pragma unroll
            for (int q = 0; q < NXF4; q++)
                *(float4*)&xv[q * 4] = *(const float4*)&xrow[swz(tx * 2 + q) << 2];
            ull xb[NX];
#pragma unroll
            for (int p = 0; p < NX; p++) PACKB(xb[p], xv[p]);
#pragma unroll
            for (int j = 0; j < K; j++) {
                const float* wrow = wsb + (cc * K + j) * 128 + cb;
                ulonglong2 w01 = *(const ulonglong2*)&wrow[0];
                ulonglong2 w23 = *(const ulonglong2*)&wrow[4];
                ull wp[4] = {w01.x, w01.y, w23.x, w23.y};
#pragma unroll
                for (int rp = 0; rp < 4; rp++)
#pragma unroll
                    for (int lt = 0; lt < 8; lt++)
                        FMA2(acc2[rp][lt], wp[rp], xb[lt + j]);
            }
        }
        if (++st == 3) st = 0;
    }

    float accs[8][8];
#pragma unroll
    for (int rp = 0; rp < 4; rp++)
#pragma unroll
        for (int lt = 0; lt < 8; lt++)
            UNPACK2(accs[2 * rp][lt], accs[2 * rp + 1][lt], acc2[rp][lt]);

#pragma unroll
    for (int r = 0; r < 8; r++) {
        float o[8];
#pragma unroll
        for (int lt = 0; lt < 8; lt++) {
            float a = accs[r][lt];
            if (ELU) a = a > 0.f ? a : expm1f(a);
            o[lt] = a;
        }
        float* base = &y[((size_t)b * COUT + co0 + cb + r) * TLEN + t0 + tb];
        *(float4*)base = *(float4*)&o[0];
        *(float4*)(base + 4) = *(float4*)&o[4];
    }
}

// ---------------- VQ (proven, no z_q store) ----------------
#define VQ_ZT 0
#define VQ_CB0 8192
#define VQ_CB1 (8192 + 8448)
#define VQ_CNORM (8192 + 16896)
#define VQ_ZN (VQ_CNORM + 1024)
#define VQ_BI (VQ_ZN + 128)
#define VQ_FLOATS (VQ_BI + 128)
#define VQ_BYTES (VQ_FLOATS * 4)
#define VQ_RV VQ_CB0
#define VQ_RI (VQ_CB0 + 2048)
#define VQ_LS VQ_CNORM

__global__ __launch_bounds__(256, 2)
void vq_kernel(const float* __restrict__ x5, const float* __restrict__ cbk,
               const float* __restrict__ cnormG,
               float* __restrict__ out_a, float* __restrict__ partial) {
    extern __shared__ float smem[];
    const uint32_t sb = smem_u32(smem);
    float* ztT = smem + VQ_ZT;
    float* cnormS = smem + VQ_CNORM;
    float* znorm = smem + VQ_ZN;
    int* besti = (int*)(smem + VQ_BI);
    float* redv = smem + VQ_RV;
    int* redi = (int*)(smem + VQ_RI);
    float* lscr = smem + VQ_LS;

    const int b = blockIdx.z, g = blockIdx.y;
    const int t0 = blockIdx.x * 128;
    const int tid = threadIdx.x;
    const int tx = tid & 15, ty = tid >> 4;
    const int trow = tx * 8, cbase = ty * 8;

    for (int i = tid; i < 8192; i += 256) {
        int d = i >> 7, lt = i & 127;
        cp4(sb + (uint32_t)(VQ_ZT + d * 128 + swzf(lt)) * 4u,
            x5 + (((size_t)b * 512) + (g << 6) + d) * TLEN + t0 + lt, true);
    }
    cp16(sb + (uint32_t)(VQ_CNORM + tid * 4) * 4u, cnormG + g * 1024 + tid * 4);
    for (int i = tid; i < 8192; i += 256) {
        int kk = i >> 6, d = i & 63;
        cp4(sb + (uint32_t)(VQ_CB0 + d * 132 + kk) * 4u,
            cbk + ((size_t)g * 1024 + kk) * 64 + d, true);
    }
    CP_COMMIT();

    float zn[8], bv[8];
    int bi8[8];
#pragma unroll
    for (int a = 0; a < 8; a++) { bv[a] = 3.4e38f; bi8[a] = 0; }

#pragma unroll 1
    for (int c = 0; c < 8; c++) {
        const int k0 = c << 7;
        if (c + 1 < 8) {
            const int koff = (c + 1) << 7;
            uint32_t cbB = sb + (uint32_t)(((c + 1) & 1) ? VQ_CB1 : VQ_CB0) * 4u;
            for (int i = tid; i < 8192; i += 256) {
                int kk = i >> 6, d = i & 63;
                cp4(cbB + (uint32_t)(d * 132 + kk) * 4u,
                    cbk + ((size_t)g * 1024 + koff + kk) * 64 + d, true);
            }
            CP_COMMIT();
            CP_WAIT(1);
        } else {
            CP_WAIT(0);
        }
        __syncthreads();

        if (c == 0) {
            if (tid < 128) {
                float s = 0.f;
                int off = swzf(tid);
#pragma unroll 8
                for (int d = 0; d < 64; d++) { float v = ztT[d * 128 + off]; s += v * v; }
                znorm[tid] = s;
            }
            __syncthreads();
#pragma unroll
            for (int a = 0; a < 8; a++) zn[a] = znorm[trow + a];
        }

        const float* ct = smem + ((c & 1) ? VQ_CB1 : VQ_CB0);
        ull acc2[8][4];
#pragma unroll
        for (int a = 0; a < 8; a++)
#pragma unroll
            for (int q = 0; q < 4; q++) acc2[a][q] = 0ull;

#pragma unroll 4
        for (int d = 0; d < 64; d++) {
            float zz[8];
            *(float4*)&zz[0] = *(const float4*)&ztT[d * 128 + (swz(tx * 2) << 2)];
            *(float4*)&zz[4] = *(const float4*)&ztT[d * 128 + (swz(tx * 2 + 1) << 2)];
            ull zb[8];
#pragma unroll
            for (int a = 0; a < 8; a++) PACKB(zb[a], zz[a]);
            ulonglong2 c01 = *(const ulonglong2*)&ct[d * 132 + cbase];
            ulonglong2 c23 = *(const ulonglong2*)&ct[d * 132 + cbase + 4];
            ull cp_[4] = {c01.x, c01.y, c23.x, c23.y};
#pragma unroll
            for (int a = 0; a < 8; a++)
#pragma unroll
                for (int q = 0; q < 4; q++)
                    FMA2(acc2[a][q], zb[a], cp_[q]);
        }

        float accs[8][8];
#pragma unroll
        for (int a = 0; a < 8; a++)
#pragma unroll
            for (int q = 0; q < 4; q++)
                UNPACK2(accs[a][2 * q], accs[a][2 * q + 1], acc2[a][q]);

        float cn[8];
#pragma unroll
        for (int cc = 0; cc < 8; cc++) cn[cc] = cnormS[k0 + cbase + cc];
#pragma unroll
        for (int a = 0; a < 8; a++) {
#pragma unroll
            for (int cc = 0; cc < 8; cc++) {
                float dist = zn[a] + cn[cc] - 2.f * accs[a][cc];
                int idx = k0 + cbase + cc;
                if (dist < bv[a]) { bv[a] = dist; bi8[a] = idx; }
            }
        }
        __syncthreads();
    }

#pragma unroll
    for (int a = 0; a < 8; a++) {
        int tok = trow + a;
        redv[tok * 16 + ty] = bv[a];
        redi[tok * 16 + ty] = bi8[a];
    }
    __syncthreads();
    if (tid < 128) {
        float best = redv[tid * 16];
        int bidx = redi[tid * 16];
#pragma unroll
        for (int s = 1; s < 16; s++) {
            float v = redv[tid * 16 + s];
            int ii = redi[tid * 16 + s];
            if (v < best || (v == best && ii < bidx)) { best = v; bidx = ii; }
        }
        besti[tid] = bidx;
        out_a[((size_t)b * 8 + g) * TLEN + t0 + tid] = (float)bidx;
    }
    __syncthreads();

    float ls = 0.f;
    for (int i = tid; i < 64 * 128; i += 256) {
        int d = i & 63, lt = i >> 6;
        float qv = cbk[((size_t)g * 1024 + besti[lt]) * 64 + d];
        float df = qv - ztT[d * 128 + swzf(lt)];
        ls += df * df;
    }
    lscr[tid] = ls;
    __syncthreads();
    for (int s = 128; s > 0; s >>= 1) {
        if (tid < s) lscr[tid] += lscr[tid + s];
        __syncthreads();
    }
    if (tid == 0)
        partial[((size_t)b * 8 + g) * 32 + blockIdx.x] = lscr[0];
}

// ---------------- launch ----------------
extern "C" void kernel_launch(void* const* d_in, const int* in_sizes, int n_in,
                              void* d_out, int out_size) {
    const float* audio = (const float*)d_in[0];
    const float* w1 = (const float*)d_in[1];
    const float* b1 = (const float*)d_in[2];
    const float* w2 = (const float*)d_in[3];
    const float* b2 = (const float*)d_in[4];
    const float* w3 = (const float*)d_in[5];
    const float* b3 = (const float*)d_in[6];
    const float* w4 = (const float*)d_in[7];
    const float* b4 = (const float*)d_in[8];
    const float* w5 = (const float*)d_in[9];
    const float* b5 = (const float*)d_in[10];
    const float* codebooks = (const float*)d_in[11];
    const float* head_w = (const float*)d_in[12];
    const float* head_b = (const float*)d_in[13];
    float* out = (float*)d_out;

    float *x2, *x3, *x4, *x5, *w2T, *w3T, *w4T, *w5T, *hwT, *cnm, *Lt, *part;
    cudaGetSymbolAddress((void**)&x2, g_x2);
    cudaGetSymbolAddress((void**)&x3, g_x3);
    cudaGetSymbolAddress((void**)&x4, g_x4);
    cudaGetSymbolAddress((void**)&x5, g_x5);
    cudaGetSymbolAddress((void**)&w2T, g_w2T);
    cudaGetSymbolAddress((void**)&w3T, g_w3T);
    cudaGetSymbolAddress((void**)&w4T, g_w4T);
    cudaGetSymbolAddress((void**)&w5T, g_w5T);
    cudaGetSymbolAddress((void**)&hwT, g_hwT);
    cudaGetSymbolAddress((void**)&cnm, g_cnorm);
    cudaGetSymbolAddress((void**)&Lt, g_L);
    cudaGetSymbolAddress((void**)&part, g_part);

    const int SM_C3 = (3 * (8 * 136 + 8 * 5 * 128)) * 4;
    const int SM_C4 = (3 * (16 * 136 + 16 * 3 * 128)) * 4;
    const int SM_C5 = SM_C4;
    const int SM_CL = (2 * 64 * 132) * 4;

    cudaFuncSetAttribute((const void*)conv12_kernel,
                         cudaFuncAttributeMaxDynamicSharedMemorySize, C12_BYTES);
    cudaFuncSetAttribute((const void*)conv_gemm<128, 256, 5, 8, 1>,
                         cudaFuncAttributeMaxDynamicSharedMemorySize, SM_C3);
    cudaFuncSetAttribute((const void*)conv_gemm<256, 512, 3, 16, 1>,
                         cudaFuncAttributeMaxDynamicSharedMemorySize, SM_C4);
    cudaFuncSetAttribute((const void*)conv_gemm<512, 512, 3, 16, 0>,
                         cudaFuncAttributeMaxDynamicSharedMemorySize, SM_C5);
    cudaFuncSetAttribute((const void*)codelogits_kernel,
                         cudaFuncAttributeMaxDynamicSharedMemorySize, SM_CL);
    cudaFuncSetAttribute((const void*)vq_kernel,
                         cudaFuncAttributeMaxDynamicSharedMemorySize, VQ_BYTES);

    prep_kernel<<<(N_PREP + 255) / 256, 256>>>(w2, w3, w4, w5, head_w, codebooks,
                                               w2T, w3T, w4T, w5T, hwT, cnm);
    codelogits_kernel<<<dim3(8, 2, 8), 256, SM_CL>>>(codebooks, hwT, Lt);

    conv12_kernel<<<dim3(32, 1, 8), 256, C12_BYTES>>>(audio, w1, b1, w2T, b2, x2);
    conv_gemm<128, 256, 5, 8, 1><<<dim3(32, 2, 8), 256, SM_C3>>>(x2, w3T, b3, x3);
    conv_gemm<256, 512, 3, 16, 1><<<dim3(32, 4, 8), 256, SM_C4>>>(x3, w4T, b4, x4);
    conv_gemm<512, 512, 3, 16, 0><<<dim3(32, 4, 8), 256, SM_C5>>>(x4, w5T, b5, x5);

    vq_kernel<<<dim3(32, 8, 8), 256, VQ_BYTES>>>(x5, codebooks, cnm,
                                                 out + OFF_A, part);
    glogits_kernel<<<1025, 256>>>(out + OFF_A, Lt, head_b, out + OFF_B,
                                  part, out + OFF_L);
}